// round 15
// baseline (speedup 1.0000x reference)
#include <cuda_runtime.h>
#include <cuda_bf16.h>
#include <stdint.h>

#define E_DIM 128
#define TT 64
#define NTHREADS 512
#define NTILES 16
// smem strides in bf16 elements
#define SW_STR 136
#define SM_STR 136
#define SU_STR 136
#define SV_STR 72

// byte offsets from 1024-aligned smem base
#define OFF_WH 0u
#define OFF_WL 34816u
#define OFF_MH 69632u
#define OFF_ML 87040u
#define OFF_V0 104448u          /* VH(buf) = OFF_V0 + buf*36864, VL = +18432 */
#define OFF_UH 178176u
#define OFF_UL 195584u
#define OFF_SUM 212992u
#define OFF_RED 213504u         /* 512 float2 = 4 KB */
#define SMEM_REQ (217600 + 1024)

// v^T split, shared by all batches: [E rows][1024 t cols]
__device__ __nv_bfloat16 g_vT_hi[E_DIM * 1024];
__device__ __nv_bfloat16 g_vT_lo[E_DIM * 1024];

__device__ __forceinline__ uint32_t s2u(const void* p) {
    uint32_t a;
    asm("{ .reg .u64 t; cvta.to.shared.u64 t, %1; cvt.u32.u64 %0, t; }" : "=r"(a) : "l"(p));
    return a;
}
__device__ __forceinline__ void ldsm_x4(uint32_t* r, uint32_t a) {
    asm volatile("ldmatrix.sync.aligned.m8n8.x4.shared.b16 {%0,%1,%2,%3}, [%4];"
                 : "=r"(r[0]), "=r"(r[1]), "=r"(r[2]), "=r"(r[3]) : "r"(a));
}
__device__ __forceinline__ void ldsm_x4t(uint32_t* r, uint32_t a) {
    asm volatile("ldmatrix.sync.aligned.m8n8.x4.trans.shared.b16 {%0,%1,%2,%3}, [%4];"
                 : "=r"(r[0]), "=r"(r[1]), "=r"(r[2]), "=r"(r[3]) : "r"(a));
}
__device__ __forceinline__ void mma16816(float* c, const uint32_t* a, const uint32_t* b) {
    asm volatile("mma.sync.aligned.m16n8k16.row.col.f32.bf16.bf16.f32 "
                 "{%0,%1,%2,%3}, {%4,%5,%6,%7}, {%8,%9}, {%0,%1,%2,%3};"
                 : "+f"(c[0]), "+f"(c[1]), "+f"(c[2]), "+f"(c[3])
                 : "r"(a[0]), "r"(a[1]), "r"(a[2]), "r"(a[3]), "r"(b[0]), "r"(b[1]));
}
__device__ __forceinline__ void cp16(uint32_t dst, const void* src) {
    asm volatile("cp.async.cg.shared.global [%0], [%1], 16;" :: "r"(dst), "l"(src));
}
#define CP_COMMIT() asm volatile("cp.async.commit_group;" ::: "memory")
#define CP_WAIT0()  asm volatile("cp.async.wait_group 0;" ::: "memory")

__device__ __forceinline__ uint32_t pkbf2(__nv_bfloat16 a, __nv_bfloat16 b) {
    __nv_bfloat162 t = __halves2bfloat162(a, b);
    return *(uint32_t*)&t;
}
__device__ __forceinline__ void split2(float x0, float x1, uint32_t& hi, uint32_t& lo) {
    __nv_bfloat16 h0 = __float2bfloat16(x0);
    __nv_bfloat16 h1 = __float2bfloat16(x1);
    hi = pkbf2(h0, h1);
    lo = pkbf2(__float2bfloat16(x0 - __bfloat162float(h0)),
               __float2bfloat16(x1 - __bfloat162float(h1)));
}
__device__ __forceinline__ float tanh_fast(float x) {
    float ex = __expf(2.0f * x);
    return 1.0f - __fdividef(2.0f, ex + 1.0f);
}

// ---------------- precompute: split v^T ----------------
__global__ void vsplit_kernel(const float* __restrict__ gv) {
    int w = blockIdx.x * blockDim.x + threadIdx.x;   // 0 .. 131071
    int e = w >> 10, t = w & 1023;
    float x = gv[t * E_DIM + e];
    __nv_bfloat16 h = __float2bfloat16(x);
    g_vT_hi[w] = h;
    g_vT_lo[w] = __float2bfloat16(x - __bfloat162float(h));
}

// ---------------- main kernel ----------------
__global__ void __launch_bounds__(NTHREADS, 1)
attn_mv_mma(const float* __restrict__ gm, const float* __restrict__ gW,
            const float* __restrict__ gb, float* __restrict__ gout)
{
    extern __shared__ char raw[];
    char* base = (char*)(((uintptr_t)raw + 1023) & ~(uintptr_t)1023);
    const uint32_t sb = s2u(base);
    float*  sSum = (float*)(base + OFF_SUM);
    float2* sRed = (float2*)(base + OFF_RED);

    const int b    = blockIdx.x;
    const int tid  = threadIdx.x;
    const int lane = tid & 31;
    const int wid  = tid >> 5;

    const float* mb = gm + (size_t)b * 1024 * E_DIM;

    // ---- stage W split into smem [e rows][f cols], hi/lo ----
    {
        const float4* W4 = (const float4*)(gW + (size_t)b * E_DIM * E_DIM);
        #pragma unroll
        for (int i = tid; i < E_DIM * 32; i += NTHREADS) {
            int e  = i >> 5;
            int f4 = (i & 31) * 4;
            float4 w = W4[i];
            uint32_t h0, l0, h1, l1;
            split2(w.x, w.y, h0, l0);
            split2(w.z, w.w, h1, l1);
            uint32_t off = (uint32_t)(e * SW_STR + f4) * 2u;
            *(uint2*)(base + OFF_WH + off) = make_uint2(h0, h1);
            *(uint2*)(base + OFF_WL + off) = make_uint2(l0, l1);
        }
    }
    if (tid < E_DIM) sSum[tid] = 0.0f;
    __syncthreads();

    const int lrow = lane & 15;
    const int lcol = (lane >> 4) * 8;
    const int e4c  = (tid & 31) * 4;

    // GEMM1 warp tiling: 4(t) x 4(f); GEMM2: 4(e) x 4(f), 32x32 per warp
    const int tb = wid & 3;
    const int fq = wid >> 2;
    const int aw = wid & 3;        // GEMM2 e-block (32 rows)
    const int fw = wid >> 2;       // GEMM2 f-block (32 cols)

    // P accumulators: rows aw*32 + rb*16 + {lane-mapped}, cols fw*32 + cb*8
    float P[2][4][4];
    #pragma unroll
    for (int rb = 0; rb < 2; ++rb)
        #pragma unroll
        for (int cb = 0; cb < 4; ++cb)
            #pragma unroll
            for (int j = 0; j < 4; ++j) P[rb][cb][j] = 0.0f;

    float4 mreg[4];   // m tile staging (needs in-register split)

    auto ldg_tile = [&](int tile, int vbuf) {
        // v^T hi/lo: direct global->smem, no registers
        uint32_t vb = sb + OFF_V0 + (uint32_t)vbuf * 36864u;
        #pragma unroll
        for (int k = 0; k < 2; ++k) {
            int i = tid + k * NTHREADS;
            int e = i >> 3, c = i & 7;
            uint32_t off = (uint32_t)(e * SV_STR * 2 + c * 16);
            cp16(vb + off,          (const char*)(g_vT_hi + (size_t)e * 1024 + tile * TT) + c * 16);
            cp16(vb + 18432u + off, (const char*)(g_vT_lo + (size_t)e * 1024 + tile * TT) + c * 16);
        }
        CP_COMMIT();
        const float4* m4 = (const float4*)(mb + (size_t)tile * TT * E_DIM);
        #pragma unroll
        for (int k = 0; k < 4; ++k) mreg[k] = m4[tid + k * NTHREADS];
    };
    auto sts_m = [&]() {
        float c0 = 0.f, c1 = 0.f, c2 = 0.f, c3 = 0.f;
        #pragma unroll
        for (int k = 0; k < 4; ++k) {
            int i  = tid + k * NTHREADS;
            int t  = i >> 5;
            int e4 = (i & 31) * 4;
            float4 a = mreg[k];
            uint32_t h0, l0, h1, l1;
            split2(a.x, a.y, h0, l0);
            split2(a.z, a.w, h1, l1);
            uint32_t off = (uint32_t)(t * SM_STR + e4) * 2u;
            *(uint2*)(base + OFF_MH + off) = make_uint2(h0, h1);
            *(uint2*)(base + OFF_ML + off) = make_uint2(l0, l1);
            c0 += a.x; c1 += a.y; c2 += a.z; c3 += a.w;
        }
        atomicAdd(&sSum[e4c + 0], c0);
        atomicAdd(&sSum[e4c + 1], c1);
        atomicAdd(&sSum[e4c + 2], c2);
        atomicAdd(&sSum[e4c + 3], c3);
    };

    // prologue: tile 0
    ldg_tile(0, 0);
    sts_m();
    CP_WAIT0();
    int buf = 0;

    for (int tile = 0; tile < NTILES; ++tile) {
        __syncthreads();   // sM, sV[buf] visible; sU free

        // ---- bias prefetch (L2-resident, time-indexed) ----
        const int r0g1 = tb * 16 + (lane >> 2);
        float2 bz[8];
        {
            const float* bp = gb + (size_t)(tile * TT + r0g1) * E_DIM;
            #pragma unroll
            for (int p = 0; p < 2; ++p)
                #pragma unroll
                for (int j = 0; j < 2; ++j) {
                    int col = fq * 32 + p * 16 + j * 8 + (lane & 3) * 2;
                    bz[(2 * p + j) * 2 + 0] = *(const float2*)(bp + col);
                    bz[(2 * p + j) * 2 + 1] = *(const float2*)(bp + 8 * E_DIM + col);
                }
        }

        // ---- GEMM1: u[64,128] = m @ W, 3-term split ----
        float acc[4][4];
        #pragma unroll
        for (int q = 0; q < 4; ++q)
            #pragma unroll
            for (int j = 0; j < 4; ++j) acc[q][j] = 0.0f;

        #pragma unroll
        for (int k0 = 0; k0 < 128; k0 += 16) {
            uint32_t ah[4], al[4];
            uint32_t ao = (uint32_t)((tb * 16 + lrow) * SM_STR + k0 + lcol) * 2u;
            ldsm_x4(ah, sb + OFF_MH + ao);
            ldsm_x4(al, sb + OFF_ML + ao);
            const int brow = k0 + lrow;
            #pragma unroll
            for (int p = 0; p < 2; ++p) {
                int n0 = fq * 32 + p * 16;
                uint32_t bo = (uint32_t)(brow * SW_STR + n0 + lcol) * 2u;
                uint32_t bh[4], bl[4];
                ldsm_x4t(bh, sb + OFF_WH + bo);
                ldsm_x4t(bl, sb + OFF_WL + bo);
                mma16816(acc[2 * p],     ah, bh);
                mma16816(acc[2 * p],     ah, bl);
                mma16816(acc[2 * p],     al, bh);
                mma16816(acc[2 * p + 1], ah, bh + 2);
                mma16816(acc[2 * p + 1], ah, bl + 2);
                mma16816(acc[2 * p + 1], al, bh + 2);
            }
        }

        // ---- epilogue: u = tanh(acc + bias), split -> sU hi/lo ----
        #pragma unroll
        for (int p = 0; p < 2; ++p)
            #pragma unroll
            for (int j = 0; j < 2; ++j) {
                int q = 2 * p + j;
                int col = fq * 32 + p * 16 + j * 8 + (lane & 3) * 2;
                float u0 = tanh_fast(acc[q][0] + bz[2 * q].x);
                float u1 = tanh_fast(acc[q][1] + bz[2 * q].y);
                float u2 = tanh_fast(acc[q][2] + bz[2 * q + 1].x);
                float u3 = tanh_fast(acc[q][3] + bz[2 * q + 1].y);
                uint32_t h0, l0, h1, l1;
                split2(u0, u1, h0, l0);
                split2(u2, u3, h1, l1);
                uint32_t o0 = (uint32_t)(r0g1 * SU_STR + col) * 2u;
                uint32_t o1 = (uint32_t)((r0g1 + 8) * SU_STR + col) * 2u;
                *(uint32_t*)(base + OFF_UH + o0) = h0;
                *(uint32_t*)(base + OFF_UL + o0) = l0;
                *(uint32_t*)(base + OFF_UH + o1) = h1;
                *(uint32_t*)(base + OFF_UL + o1) = l1;
            }
        __syncthreads();   // sU ready; all GEMM1 reads of sM done

        // ---- prefetch next tile (latency hides under GEMM2) ----
        const bool pf = (tile + 1 < NTILES);
        if (pf) ldg_tile(tile + 1, buf ^ 1);

        // ---- GEMM2: P(32x32/warp) += vT @ u, 3-term split ----
        const uint32_t vbh = sb + OFF_V0 + (uint32_t)buf * 36864u;
        #pragma unroll
        for (int k0 = 0; k0 < 64; k0 += 16) {
            uint32_t ah[2][4], al[2][4];
            #pragma unroll
            for (int rb = 0; rb < 2; ++rb) {
                uint32_t ao = (uint32_t)((aw * 32 + rb * 16 + lrow) * SV_STR + k0 + lcol) * 2u;
                ldsm_x4(ah[rb], vbh + ao);
                ldsm_x4(al[rb], vbh + 18432u + ao);
            }
            const int brow = k0 + lrow;
            #pragma unroll
            for (int p = 0; p < 2; ++p) {
                uint32_t bo = (uint32_t)(brow * SU_STR + fw * 32 + p * 16 + lcol) * 2u;
                uint32_t bh[4], bl[4];
                ldsm_x4t(bh, sb + OFF_UH + bo);
                ldsm_x4t(bl, sb + OFF_UL + bo);
                #pragma unroll
                for (int rb = 0; rb < 2; ++rb) {
                    mma16816(P[rb][2 * p],     ah[rb], bh);
                    mma16816(P[rb][2 * p],     ah[rb], bl);
                    mma16816(P[rb][2 * p],     al[rb], bh);
                    mma16816(P[rb][2 * p + 1], ah[rb], bh + 2);
                    mma16816(P[rb][2 * p + 1], ah[rb], bl + 2);
                    mma16816(P[rb][2 * p + 1], al[rb], bh + 2);
                }
            }
        }

        if (pf) { sts_m(); CP_WAIT0(); }
        buf ^= 1;
    }

    // ---- softmax rows of P (4 f-block warps per row) + weighting ----
    float* sP = (float*)base;   // reuse W/M region
    {
        const int lr = lane >> 2;               // 0..7
        // this lane's 4 rows: aw*32 + lr + {0, 8, 16, 24}
        float mx[4] = {-3.4e38f, -3.4e38f, -3.4e38f, -3.4e38f};
        #pragma unroll
        for (int rb = 0; rb < 2; ++rb)
            #pragma unroll
            for (int cb = 0; cb < 4; ++cb) {
                mx[rb * 2 + 0] = fmaxf(mx[rb * 2 + 0], fmaxf(P[rb][cb][0], P[rb][cb][1]));
                mx[rb * 2 + 1] = fmaxf(mx[rb * 2 + 1], fmaxf(P[rb][cb][2], P[rb][cb][3]));
            }
        #pragma unroll
        for (int r = 0; r < 4; ++r) {
            mx[r] = fmaxf(mx[r], __shfl_xor_sync(0xffffffffu, mx[r], 1));
            mx[r] = fmaxf(mx[r], __shfl_xor_sync(0xffffffffu, mx[r], 2));
        }
        float sm[4] = {0.f, 0.f, 0.f, 0.f};
        #pragma unroll
        for (int rb = 0; rb < 2; ++rb)
            #pragma unroll
            for (int cb = 0; cb < 4; ++cb) {
                P[rb][cb][0] = __expf(P[rb][cb][0] - mx[rb * 2 + 0]);
                P[rb][cb][1] = __expf(P[rb][cb][1] - mx[rb * 2 + 0]);
                P[rb][cb][2] = __expf(P[rb][cb][2] - mx[rb * 2 + 1]);
                P[rb][cb][3] = __expf(P[rb][cb][3] - mx[rb * 2 + 1]);
                sm[rb * 2 + 0] += P[rb][cb][0] + P[rb][cb][1];
                sm[rb * 2 + 1] += P[rb][cb][2] + P[rb][cb][3];
            }
        #pragma unroll
        for (int r = 0; r < 4; ++r) {
            sm[r] += __shfl_xor_sync(0xffffffffu, sm[r], 1);
            sm[r] += __shfl_xor_sync(0xffffffffu, sm[r], 2);
        }
        // rows in r-index order: r=0 -> +0, r=1 -> +8 (rb0 frags 2,3), r=2 -> +16, r=3 -> +24
        const int rofs[4] = {0, 8, 16, 24};
        if ((lane & 3) == 0) {
            #pragma unroll
            for (int r = 0; r < 4; ++r) {
                int row = aw * 32 + lr + rofs[r];
                sRed[row * 4 + fw] = make_float2(mx[r], sm[r]);
            }
        }
        __syncthreads();
        float sc[4];
        #pragma unroll
        for (int r = 0; r < 4; ++r) {
            int row = aw * 32 + lr + rofs[r];
            float2 p0 = sRed[row * 4 + 0], p1 = sRed[row * 4 + 1];
            float2 p2 = sRed[row * 4 + 2], p3 = sRed[row * 4 + 3];
            float M = fmaxf(fmaxf(p0.x, p1.x), fmaxf(p2.x, p3.x));
            float S = p0.y * __expf(p0.x - M) + p1.y * __expf(p1.x - M)
                    + p2.y * __expf(p2.x - M) + p3.y * __expf(p3.x - M);
            sc[r] = __expf(mx[r] - M) * sSum[row] / S;
        }
        #pragma unroll
        for (int rb = 0; rb < 2; ++rb)
            #pragma unroll
            for (int cb = 0; cb < 4; ++cb) {
                int col = fw * 32 + cb * 8 + (lane & 3) * 2;
                int rowA = aw * 32 + lr + rb * 16;
                *(float2*)(sP + rowA * E_DIM + col) =
                    make_float2(P[rb][cb][0] * sc[rb * 2], P[rb][cb][1] * sc[rb * 2]);
                *(float2*)(sP + (rowA + 8) * E_DIM + col) =
                    make_float2(P[rb][cb][2] * sc[rb * 2 + 1], P[rb][cb][3] * sc[rb * 2 + 1]);
            }
    }
    __syncthreads();

    if (tid < E_DIM) {
        float o = 0.0f;
        #pragma unroll 8
        for (int e = 0; e < E_DIM; ++e) o += sP[e * E_DIM + tid];
        gout[(size_t)b * E_DIM + tid] = o;
    }
}

extern "C" void kernel_launch(void* const* d_in, const int* in_sizes, int n_in,
                              void* d_out, int out_size)
{
    const float* m  = (const float*)d_in[0];   // (B, T, E)
    const float* v  = (const float*)d_in[1];   // (T, E)   time-indexed
    const float* W  = (const float*)d_in[2];   // (B, E, E)
    const float* bb = (const float*)d_in[3];   // (T, E)   bias, time-indexed
    float* out = (float*)d_out;                // (B, E)

    const int BE = in_sizes[1];
    const int Bn = BE / E_DIM;                 // 1024

    vsplit_kernel<<<(1024 * E_DIM) / 256, 256>>>(v);

    cudaFuncSetAttribute(attn_mv_mma, cudaFuncAttributeMaxDynamicSharedMemorySize, SMEM_REQ);
    attn_mv_mma<<<Bn, NTHREADS, SMEM_REQ>>>(m, W, bb, out);
}